// round 16
// baseline (speedup 1.0000x reference)
#include <cuda_runtime.h>
#include <cuda_bf16.h>
#include <cuda_fp16.h>
#include <math.h>
#include <stdint.h>

// Problem constants (match reference)
#define MAXN 10000
#define MAXE 40000
#define MAXG 128
#define NF 92
#define EF 50
#define HD 64
#define NHEAD 10
#define GD 108
#define NL 5
#define HW (NHEAD*HD)   // 640

// ---------------- static device scratch (no allocations allowed) -------------
__device__ float g_h[MAXN*HD];
__device__ float g_h0[MAXN*HD];
__device__ float g_ea[MAXE*HD];
__device__ __half g_Ph[MAXN*HW];           // fp16 P (gathered twice per edge)
__device__ __half g_Qh[(size_t)MAXE*HW];   // fp16 Q (write-once read-once stream)
__device__ float g_hagg[MAXN*HD];          // zero-init; re-zeroed by node_update
__device__ float g_GB[MAXG*HD];
__device__ float g_score[MAXN];
__device__ float g_ex[MAXN];
__device__ unsigned g_smax[MAXG];
__device__ float g_denom[MAXG];
__device__ float g_pooled[MAXG*HD];
// tf32 operands (fp32 storage, tf32-rounded, fragment-pair-permuted layout)
__device__ float g_Wt[NL*2*HW*HD];   // [L*2][n=640][j=64]
__device__ float g_eat[MAXE*HD];
__device__ float g_ht[MAXN*HD];

__device__ __forceinline__ float lrelu(float v) { return v > 0.f ? v : 0.2f * v; }

__device__ __forceinline__ unsigned f2o(float f) {
    unsigned u = __float_as_uint(f);
    return (u & 0x80000000u) ? ~u : (u | 0x80000000u);
}
__device__ __forceinline__ float o2f(unsigned u) {
    return (u & 0x80000000u) ? __uint_as_float(u ^ 0x80000000u) : __uint_as_float(~u);
}

__device__ __forceinline__ float tf32_rnd(float v) {
    uint32_t r;
    asm("cvt.rna.tf32.f32 %0, %1;" : "=r"(r) : "f"(v));
    return __uint_as_float(r);
}

// fragment-pair permutation: position j in a row holds original k-index:
//   ks = j>>3, r = j&7  ->  k = ks*8 + (r>>1) + (r&1)*4
__device__ __forceinline__ int orig_col(int j) {
    int ks = j >> 3, r = j & 7;
    return ks * 8 + (r >> 1) + (r & 1) * 4;
}
// inverse: position j that holds original k
__device__ __forceinline__ int perm_col(int k) {
    int ks = k >> 3, q = k & 7;
    return ks * 8 + ((q & 3) << 1) + (q >> 2);
}

// tf32 HMMA m16n8k8 (baseline mma.sync; supported on sm_103 non-'a' target)
__device__ __forceinline__ void mma_tf32(float* c, const uint32_t* a, const uint32_t* b) {
    asm volatile(
        "mma.sync.aligned.m16n8k8.row.col.f32.tf32.tf32.f32 "
        "{%0,%1,%2,%3}, {%4,%5,%6,%7}, {%8,%9}, {%0,%1,%2,%3};"
        : "+f"(c[0]), "+f"(c[1]), "+f"(c[2]), "+f"(c[3])
        : "r"(a[0]), "r"(a[1]), "r"(a[2]), "r"(a[3]), "r"(b[0]), "r"(b[1]));
}

// ---------------- prep kernels ----------------------------------------------
__global__ void prep_W(const float* __restrict__ W)
{
    int idx = blockIdx.x * blockDim.x + threadIdx.x;
    if (idx >= NL * 2 * HW * HD) return;
    int j  = idx & 63;
    int t  = idx >> 6;
    int n  = t % HW;
    int t2 = t / HW;
    float v = W[((size_t)t2 * HD + orig_col(j)) * HW + n];
    g_Wt[((size_t)t2 * HW + n) * HD + j] = tf32_rnd(v);
}

__global__ void round_perm(const float* __restrict__ src, float* __restrict__ dst, int n)
{
    int idx = blockIdx.x * blockDim.x + threadIdx.x;
    if (idx >= n) return;
    int j = idx & 63;
    int row = idx >> 6;
    dst[idx] = tf32_rnd(src[row * HD + orig_col(j)]);
}

// ---------------- tf32 HMMA fused P/Q GEMM (both outputs fp16) ---------------
// Tile 128x128; 256 thr; warp 32x64; K=64 in 8 k-steps.
__global__ __launch_bounds__(256)
void gemm_mma(const float* __restrict__ A1, const float* __restrict__ A2,
              const float* __restrict__ W1, const float* __restrict__ W2,
              __half* __restrict__ C1, __half* __restrict__ C2,
              int M1, int M2, int nb1)
{
    const float *A, *W; __half* C; int M, row0;
    if ((int)blockIdx.x < nb1) {
        A = A1; W = W1; C = C1; M = M1; row0 = blockIdx.x * 128;
    } else {
        A = A2; W = W2; C = C2; M = M2; row0 = (blockIdx.x - nb1) * 128;
    }
    const int col0 = blockIdx.y * 128;

    const int wid  = threadIdx.x >> 5;
    const int lane = threadIdx.x & 31;
    const int g    = lane >> 2;
    const int tig  = lane & 3;

    const int warp_m = wid & 3;
    const int warp_n = wid >> 2;

    float acc[2][8][4];
#pragma unroll
    for (int mf = 0; mf < 2; mf++)
#pragma unroll
        for (int nf = 0; nf < 8; nf++)
#pragma unroll
            for (int j = 0; j < 4; j++) acc[mf][nf][j] = 0.f;

    int rA[2][2];
#pragma unroll
    for (int mf = 0; mf < 2; mf++) {
        int base = row0 + warp_m * 32 + mf * 16 + g;
        rA[mf][0] = min(base,     M - 1);
        rA[mf][1] = min(base + 8, M - 1);
    }
    int nB[8];
#pragma unroll
    for (int nf = 0; nf < 8; nf++) nB[nf] = col0 + warp_n * 64 + nf * 8 + g;

#pragma unroll
    for (int ks = 0; ks < 8; ks++) {
        const int kofs = ks * 8 + tig * 2;
        uint32_t Afrag[2][4];
#pragma unroll
        for (int mf = 0; mf < 2; mf++) {
            uint2 v0 = *(const uint2*)(A + rA[mf][0] * HD + kofs);
            uint2 v1 = *(const uint2*)(A + rA[mf][1] * HD + kofs);
            Afrag[mf][0] = v0.x; Afrag[mf][2] = v0.y;
            Afrag[mf][1] = v1.x; Afrag[mf][3] = v1.y;
        }
        uint32_t Bfrag[8][2];
#pragma unroll
        for (int nf = 0; nf < 8; nf++) {
            uint2 v = *(const uint2*)(W + nB[nf] * HD + kofs);
            Bfrag[nf][0] = v.x; Bfrag[nf][1] = v.y;
        }
#pragma unroll
        for (int mf = 0; mf < 2; mf++)
#pragma unroll
            for (int nf = 0; nf < 8; nf++)
                mma_tf32(acc[mf][nf], Afrag[mf], Bfrag[nf]);
    }

#pragma unroll
    for (int mf = 0; mf < 2; mf++) {
        const int r0 = row0 + warp_m * 32 + mf * 16 + g;
#pragma unroll
        for (int nf = 0; nf < 8; nf++) {
            const int c = col0 + warp_n * 64 + nf * 8 + 2 * tig;
            if (r0 < M)
                *(__half2*)(C + (size_t)r0 * HW + c) =
                    __floats2half2_rn(acc[mf][nf][0], acc[mf][nf][1]);
            if (r0 + 8 < M)
                *(__half2*)(C + (size_t)(r0 + 8) * HW + c) =
                    __floats2half2_rn(acc[mf][nf][2], acc[mf][nf][3]);
        }
    }
}

// ---------------- tiled fp32 GEMM (embeddings) -------------------------------
__global__ void gemm_tiled(const float* __restrict__ A, int lda,
                           const float* __restrict__ W, int ldw,
                           const float* __restrict__ bias,
                           float* __restrict__ C, int ldc,
                           int M, int K, int act)
{
    __shared__ float As[16][64];
    __shared__ float Ws[16][64];
    const int row0 = blockIdx.x * 64;
    const int col0 = blockIdx.y * 64;
    const int tid = threadIdx.x;
    const int tx = tid & 15, ty = tid >> 4;

    float acc[4][4];
#pragma unroll
    for (int i = 0; i < 4; i++)
#pragma unroll
        for (int j = 0; j < 4; j++) acc[i][j] = 0.f;

    for (int k0 = 0; k0 < K; k0 += 16) {
#pragma unroll
        for (int i = 0; i < 4; i++) {
            int e = tid + 256 * i;
            int r = e >> 4, kk = e & 15;
            int gr = row0 + r, gk = k0 + kk;
            As[kk][r] = (gr < M && gk < K) ? A[(size_t)gr * lda + gk] : 0.f;
        }
#pragma unroll
        for (int i = 0; i < 4; i++) {
            int e = tid + 256 * i;
            int kk = e >> 6, c = e & 63;
            int gk = k0 + kk;
            Ws[kk][c] = (gk < K) ? W[(size_t)gk * ldw + col0 + c] : 0.f;
        }
        __syncthreads();
#pragma unroll
        for (int kk = 0; kk < 16; kk++) {
            float4 a = *(const float4*)&As[kk][ty * 4];
            float4 b = *(const float4*)&Ws[kk][tx * 4];
            float av[4] = {a.x, a.y, a.z, a.w};
            float bv[4] = {b.x, b.y, b.z, b.w};
#pragma unroll
            for (int i = 0; i < 4; i++)
#pragma unroll
                for (int j = 0; j < 4; j++) acc[i][j] += av[i] * bv[j];
        }
        __syncthreads();
    }
#pragma unroll
    for (int i = 0; i < 4; i++) {
        int r = row0 + ty * 4 + i;
        if (r >= M) continue;
#pragma unroll
        for (int j = 0; j < 4; j++) {
            int c = col0 + tx * 4 + j;
            float v = acc[i][j];
            if (bias) v += bias[c];
            if (act) v = lrelu(v);
            C[(size_t)r * ldc + c] = v;
        }
    }
}

// ---------------- per-edge GAT kernel (warp per edge, fp16 P & Q) ------------
__global__ void edge_kernel(const int* __restrict__ rowi, const int* __restrict__ coli,
                            const float* __restrict__ att,
                            const float* __restrict__ gamma,
                            const float* __restrict__ beta,
                            int E)
{
    int e = (blockIdx.x * blockDim.x + threadIdx.x) >> 5;
    if (e >= E) return;
    const int l = threadIdx.x & 31;
    const int r = rowi[e], c = coli[e];
    const __half2* pr = (const __half2*)(g_Ph + (size_t)r * HW);
    const __half2* pc = (const __half2*)(g_Ph + (size_t)c * HW);
    const __half2* q  = (const __half2*)(g_Qh + (size_t)e * HW);
    const float2*  at = (const float2*)att;

    float2 hj[NHEAD];
    float alpha[NHEAD];
#pragma unroll
    for (int nh = 0; nh < NHEAD; nh++) {
        float2 qv  = __half22float2(q[nh * 32 + l]);
        float2 prv = __half22float2(pr[nh * 32 + l]);
        float2 pcv = __half22float2(pc[nh * 32 + l]);
        float hi0 = lrelu(prv.x + qv.x), hi1 = lrelu(prv.y + qv.y);
        float hj0 = lrelu(pcv.x + qv.x), hj1 = lrelu(pcv.y + qv.y);
        hj[nh].x = hj0; hj[nh].y = hj1;
        float2 a1 = at[nh * 64 + l];
        float2 a2 = at[nh * 64 + 32 + l];
        float part = hi0 * a1.x + hi1 * a1.y + hj0 * a2.x + hj1 * a2.y;
#pragma unroll
        for (int o = 16; o; o >>= 1) part += __shfl_xor_sync(0xffffffffu, part, o);
        alpha[nh] = part;
    }
    const float inv_std = 0.9999950000374997f;  // 1/sqrt(1+1e-5)
    float mx = -1e30f;
#pragma unroll
    for (int nh = 0; nh < NHEAD; nh++) {
        float a = lrelu(alpha[nh]);
        a = a * inv_std * gamma[nh] + beta[nh];
        alpha[nh] = a;
        mx = fmaxf(mx, a);
    }
    float s = 0.f;
#pragma unroll
    for (int nh = 0; nh < NHEAD; nh++) { float ev = expf(alpha[nh] - mx); alpha[nh] = ev; s += ev; }
    float inv = 0.1f / s;
    float m0 = 0.f, m1 = 0.f;
#pragma unroll
    for (int nh = 0; nh < NHEAD; nh++) { m0 += hj[nh].x * alpha[nh]; m1 += hj[nh].y * alpha[nh]; }
    m0 *= inv; m1 *= inv;
    atomicAdd(&g_hagg[r * HD + 2 * l],     m0);
    atomicAdd(&g_hagg[r * HD + 2 * l + 1], m1);
}

// ---------------- node update (+ zero hagg for next layer; + tf32 perm) ------
__global__ void node_update(const float* __restrict__ b, int N, int first, int last)
{
    int idx = blockIdx.x * blockDim.x + threadIdx.x;
    if (idx >= N * HD) return;
    int k = idx & (HD - 1);
    int row = idx >> 6;
    float v = g_hagg[idx] + b[k];
    g_hagg[idx] = 0.f;                       // ready for next layer / next replay
    float h = first ? v : (g_h[idx] + v);
    if (last) h += g_h0[idx];
    g_h[idx] = h;
    g_ht[row * HD + perm_col(k)] = tf32_rnd(h);
}

// ---------------- readout ----------------------------------------------------
__global__ void gb_kernel(const float* __restrict__ gf, const float* __restrict__ W1,
                          const float* __restrict__ b1, int G)
{
    int g = blockIdx.x;
    int k = threadIdx.x;
    float acc = b1[k];
    const float* gr = gf + (size_t)g * GD;
    for (int j = 0; j < GD; j++) acc += gr[j] * W1[(64 + j) * HD + k];
    g_GB[g * HD + k] = acc;
}

__global__ void score_kernel(const int* __restrict__ batch,
                             const float* __restrict__ W1,
                             const float* __restrict__ W2, const float* __restrict__ b2,
                             int N)
{
    int n = (blockIdx.x * blockDim.x + threadIdx.x) >> 5;
    if (n >= N) return;
    int l = threadIdx.x & 31;
    int b = batch[n];
    int k0 = 2 * l;
    float s0 = g_GB[b * HD + k0], s1 = g_GB[b * HD + k0 + 1];
    const float* hr = g_h + (size_t)n * HD;
#pragma unroll 8
    for (int j = 0; j < HD; j++) {
        float hv = hr[j];
        s0 += hv * W1[j * HD + k0];
        s1 += hv * W1[j * HD + k0 + 1];
    }
    s0 = lrelu(s0); s1 = lrelu(s1);
    float part = s0 * W2[k0] + s1 * W2[k0 + 1];
#pragma unroll
    for (int o = 16; o; o >>= 1) part += __shfl_xor_sync(0xffffffffu, part, o);
    if (l == 0) {
        float sc = part + b2[0];
        g_score[n] = sc;
        atomicMax(&g_smax[b], f2o(sc));
    }
}

__global__ void exp_kernel(const int* __restrict__ batch, int N)
{
    int n = blockIdx.x * blockDim.x + threadIdx.x;
    if (n >= N) return;
    int b = batch[n];
    float ev = expf(g_score[n] - o2f(g_smax[b]));
    g_ex[n] = ev;
    atomicAdd(&g_denom[b], ev);
}

__global__ void pool_kernel(const int* __restrict__ batch, int N)
{
    int n = (blockIdx.x * blockDim.x + threadIdx.x) >> 5;
    if (n >= N) return;
    int l = threadIdx.x & 31;
    int b = batch[n];
    float w = g_ex[n] / g_denom[b];
    int k0 = 2 * l;
    atomicAdd(&g_pooled[b * HD + k0],     g_h[(size_t)n * HD + k0] * w);
    atomicAdd(&g_pooled[b * HD + k0 + 1], g_h[(size_t)n * HD + k0 + 1] * w);
}

__global__ void out_kernel(const float* __restrict__ W1, const float* __restrict__ b1,
                           const float* __restrict__ W2, const float* __restrict__ b2,
                           float* __restrict__ out)
{
    int g = blockIdx.x;
    int k = threadIdx.x;
    __shared__ float ps[HD];
    __shared__ float red[HD];
    ps[k] = g_pooled[g * HD + k];
    __syncthreads();
    float acc = b1[k];
#pragma unroll 8
    for (int j = 0; j < HD; j++) acc += ps[j] * W1[j * HD + k];
    acc = fmaxf(acc, 0.f);
    red[k] = acc * W2[k];
    __syncthreads();
    for (int o = 32; o; o >>= 1) {
        if (k < o) red[k] += red[k + o];
        __syncthreads();
    }
    if (k == 0) out[g] = red[0] + b2[0];
}

// ---------------- host launcher ---------------------------------------------
extern "C" void kernel_launch(void* const* d_in, const int* in_sizes, int n_in,
                              void* d_out, int out_size)
{
    const float* x      = (const float*)d_in[0];
    const int*   eidx   = (const int*)  d_in[1];
    const float* eattr  = (const float*)d_in[2];
    const int*   batch  = (const int*)  d_in[3];
    const float* gfeat  = (const float*)d_in[4];
    const float* node_W = (const float*)d_in[5];
    const float* node_b = (const float*)d_in[6];
    const float* edge_W = (const float*)d_in[7];
    const float* edge_b = (const float*)d_in[8];
    const float* conv_W = (const float*)d_in[9];
    const float* conv_att = (const float*)d_in[10];
    const float* conv_b = (const float*)d_in[11];
    const float* conv_g = (const float*)d_in[12];
    const float* conv_be = (const float*)d_in[13];
    const float* ga_W1  = (const float*)d_in[14];
    const float* ga_b1  = (const float*)d_in[15];
    const float* ga_W2  = (const float*)d_in[16];
    const float* ga_b2  = (const float*)d_in[17];
    const float* out_W1 = (const float*)d_in[18];
    const float* out_b1 = (const float*)d_in[19];
    const float* out_W2 = (const float*)d_in[20];
    const float* out_b2 = (const float*)d_in[21];

    const int N = in_sizes[3];
    const int E = in_sizes[2] / EF;
    const int G = in_sizes[4] / GD;

    const int* row = eidx;
    const int* col = eidx + E;

    float *p_h, *p_h0, *p_ea, *p_hagg, *p_denom, *p_pooled;
    float *p_Wt, *p_eat, *p_ht;
    __half *p_Ph, *p_Qh;
    unsigned* p_smax;
    cudaGetSymbolAddress((void**)&p_h,     g_h);
    cudaGetSymbolAddress((void**)&p_h0,    g_h0);
    cudaGetSymbolAddress((void**)&p_ea,    g_ea);
    cudaGetSymbolAddress((void**)&p_Ph,    g_Ph);
    cudaGetSymbolAddress((void**)&p_Qh,    g_Qh);
    cudaGetSymbolAddress((void**)&p_hagg,  g_hagg);
    cudaGetSymbolAddress((void**)&p_smax,  g_smax);
    cudaGetSymbolAddress((void**)&p_denom, g_denom);
    cudaGetSymbolAddress((void**)&p_pooled,g_pooled);
    cudaGetSymbolAddress((void**)&p_Wt,    g_Wt);
    cudaGetSymbolAddress((void**)&p_eat,   g_eat);
    cudaGetSymbolAddress((void**)&p_ht,    g_ht);

    // embeddings (fp32)
    {
        dim3 grid((N + 63) / 64, HD / 64);
        gemm_tiled<<<grid, 256>>>(x, NF, node_W, HD, node_b, p_h0, HD, N, NF, 1);
    }
    {
        dim3 grid((E + 63) / 64, HD / 64);
        gemm_tiled<<<grid, 256>>>(eattr, EF, edge_W, HD, edge_b, p_ea, HD, E, EF, 1);
    }

    // prep: conv weights (transpose+round+perm); edge & initial node embeddings
    prep_W<<<(NL * 2 * HW * HD + 255) / 256, 256>>>(conv_W);
    round_perm<<<(E * HD + 255) / 256, 256>>>(p_ea, p_eat, E * HD);
    round_perm<<<(N * HD + 255) / 256, 256>>>(p_h0, p_ht, N * HD);

    const int nb1 = (N + 127) / 128;
    const int nb2 = (E + 127) / 128;

    for (int i = 0; i < NL; i++) {
        const float* attL = conv_att + (size_t)i * NHEAD * 2 * HD;
        const float* bL   = conv_b + i * HD;
        const float* gmL  = conv_g + i * NHEAD;
        const float* btL  = conv_be + i * NHEAD;

        const float* WP = p_Wt + (size_t)(i * 2 + 0) * HW * HD;
        const float* WQ = p_Wt + (size_t)(i * 2 + 1) * HW * HD;

        dim3 gridPQ(nb1 + nb2, HW / 128);
        gemm_mma<<<gridPQ, 256>>>(p_ht, p_eat, WP, WQ, p_Ph, p_Qh, N, E, nb1);

        int blocks = (E * 32 + 255) / 256;
        edge_kernel<<<blocks, 256>>>(row, col, attL, gmL, btL, E);

        node_update<<<(N * HD + 255) / 256, 256>>>(bL, N, i == 0, i == NL - 1);
    }

    // readout
    cudaMemsetAsync(p_smax, 0, G * sizeof(unsigned));
    cudaMemsetAsync(p_denom, 0, G * sizeof(float));
    cudaMemsetAsync(p_pooled, 0, (size_t)G * HD * sizeof(float));

    gb_kernel<<<G, HD>>>(gfeat, ga_W1, ga_b1, G);
    score_kernel<<<(N * 32 + 255) / 256, 256>>>(batch, ga_W1, ga_W2, ga_b2, N);
    exp_kernel<<<(N + 255) / 256, 256>>>(batch, N);
    pool_kernel<<<(N * 32 + 255) / 256, 256>>>(batch, N);
    out_kernel<<<G, HD>>>(out_W1, out_b1, out_W2, out_b2, (float*)d_out);
}

// round 17
// speedup vs baseline: 1.2692x; 1.2692x over previous
#include <cuda_runtime.h>
#include <cuda_bf16.h>
#include <cuda_fp16.h>
#include <math.h>
#include <stdint.h>

// Problem constants (match reference)
#define MAXN 10000
#define MAXE 40000
#define MAXG 128
#define NF 92
#define EF 50
#define HD 64
#define NHEAD 10
#define GD 108
#define NL 5
#define HW (NHEAD*HD)   // 640

#define GEMM_SMEM (128*64*2*4)   // A tile + B tile, fp32

// ---------------- static device scratch (no allocations allowed) -------------
__device__ float g_h[MAXN*HD];
__device__ float g_h0[MAXN*HD];
__device__ float g_ea[MAXE*HD];
__device__ __half g_Ph[MAXN*HW];           // fp16 P (gathered twice per edge)
__device__ __half g_Qh[(size_t)MAXE*HW];   // fp16 Q (write-once read-once stream)
__device__ float g_hagg[MAXN*HD];          // zero-init; re-zeroed by node_update
__device__ float g_GB[MAXG*HD];
__device__ float g_score[MAXN];
__device__ float g_ex[MAXN];
__device__ unsigned g_smax[MAXG];
__device__ float g_denom[MAXG];
__device__ float g_pooled[MAXG*HD];
// tf32 operands (fp32 storage, tf32-rounded, fragment-pair-permuted layout)
__device__ float g_Wt[NL*2*HW*HD];   // [L*2][n=640][j=64]
__device__ float g_eat[MAXE*HD];
__device__ float g_ht[MAXN*HD];

__device__ __forceinline__ float lrelu(float v) { return v > 0.f ? v : 0.2f * v; }

__device__ __forceinline__ unsigned f2o(float f) {
    unsigned u = __float_as_uint(f);
    return (u & 0x80000000u) ? ~u : (u | 0x80000000u);
}
__device__ __forceinline__ float o2f(unsigned u) {
    return (u & 0x80000000u) ? __uint_as_float(u ^ 0x80000000u) : __uint_as_float(~u);
}

__device__ __forceinline__ float tf32_rnd(float v) {
    uint32_t r;
    asm("cvt.rna.tf32.f32 %0, %1;" : "=r"(r) : "f"(v));
    return __uint_as_float(r);
}

// fragment-pair permutation: position j in a row holds original k-index:
//   ks = j>>3, r = j&7  ->  k = ks*8 + (r>>1) + (r&1)*4
__device__ __forceinline__ int orig_col(int j) {
    int ks = j >> 3, r = j & 7;
    return ks * 8 + (r >> 1) + (r & 1) * 4;
}
// inverse: position j that holds original k
__device__ __forceinline__ int perm_col(int k) {
    int ks = k >> 3, q = k & 7;
    return ks * 8 + ((q & 3) << 1) + (q >> 2);
}

// tf32 HMMA m16n8k8 (baseline mma.sync; supported on sm_103 non-'a' target)
__device__ __forceinline__ void mma_tf32(float* c, const uint32_t* a, const uint32_t* b) {
    asm volatile(
        "mma.sync.aligned.m16n8k8.row.col.f32.tf32.tf32.f32 "
        "{%0,%1,%2,%3}, {%4,%5,%6,%7}, {%8,%9}, {%0,%1,%2,%3};"
        : "+f"(c[0]), "+f"(c[1]), "+f"(c[2]), "+f"(c[3])
        : "r"(a[0]), "r"(a[1]), "r"(a[2]), "r"(a[3]), "r"(b[0]), "r"(b[1]));
}

// ---------------- prep kernels ----------------------------------------------
__global__ void prep_W(const float* __restrict__ W)
{
    int idx = blockIdx.x * blockDim.x + threadIdx.x;
    if (idx >= NL * 2 * HW * HD) return;
    int j  = idx & 63;
    int t  = idx >> 6;
    int n  = t % HW;
    int t2 = t / HW;
    float v = W[((size_t)t2 * HD + orig_col(j)) * HW + n];
    g_Wt[((size_t)t2 * HW + n) * HD + j] = tf32_rnd(v);
}

__global__ void round_perm(const float* __restrict__ src, float* __restrict__ dst, int n)
{
    int idx = blockIdx.x * blockDim.x + threadIdx.x;
    if (idx >= n) return;
    int j = idx & 63;
    int row = idx >> 6;
    dst[idx] = tf32_rnd(src[row * HD + orig_col(j)]);
}

// ---------------- tf32 HMMA fused P/Q GEMM (smem-staged, fp16 out) -----------
// Tile 128x128; 256 thr; warp 32x64; K=64 in 8 k-steps.
// Both operand tiles staged in smem with XOR-swizzled float2 granules:
// granule p of row r stored at p ^ ((r&7)*4)  -> conflict-free LDS.64 frags.
__global__ __launch_bounds__(256)
void gemm_mma(const float* __restrict__ A1, const float* __restrict__ A2,
              const float* __restrict__ W1, const float* __restrict__ W2,
              __half* __restrict__ C1, __half* __restrict__ C2,
              int M1, int M2, int nb1)
{
    extern __shared__ float sm[];
    float* As = sm;               // [128][64] swizzled
    float* Bs = sm + 128 * 64;    // [128][64] swizzled

    const float *A, *W; __half* C; int M, row0;
    if ((int)blockIdx.x < nb1) {
        A = A1; W = W1; C = C1; M = M1; row0 = blockIdx.x * 128;
    } else {
        A = A2; W = W2; C = C2; M = M2; row0 = (blockIdx.x - nb1) * 128;
    }
    const int col0 = blockIdx.y * 128;

    const int tid  = threadIdx.x;
    const int wid  = tid >> 5;
    const int lane = tid & 31;
    const int g    = lane >> 2;
    const int tig  = lane & 3;

    const int warp_m = wid & 3;
    const int warp_n = wid >> 2;

    // ---- stage tiles: 128 rows x 16 float4 each ----
#pragma unroll
    for (int i = 0; i < 8; i++) {
        int fi = tid + i * 256;          // 0..2047
        int r  = fi >> 4;
        int p4 = fi & 15;                // float4 index in row = granules 2p4, 2p4+1
        int sw = (p4 * 2) ^ ((r & 7) * 4);
        {   // A (row clamp)
            int gr = min(row0 + r, M - 1);
            float4 v = *(const float4*)(A + (size_t)gr * HD + p4 * 4);
            *(float4*)&As[r * 64 + sw * 2] = v;
        }
        {   // B (always in range: col0+r < 640)
            float4 v = *(const float4*)(W + (size_t)(col0 + r) * HD + p4 * 4);
            *(float4*)&Bs[r * 64 + sw * 2] = v;
        }
    }
    __syncthreads();

    float acc[2][8][4];
#pragma unroll
    for (int mf = 0; mf < 2; mf++)
#pragma unroll
        for (int nf = 0; nf < 8; nf++)
#pragma unroll
            for (int j = 0; j < 4; j++) acc[mf][nf][j] = 0.f;

#pragma unroll
    for (int ks = 0; ks < 8; ks++) {
        const int idxp = ((ks * 4 + tig) ^ (g * 4)) * 2;   // swizzled float offset
        uint32_t Afrag[2][4];
#pragma unroll
        for (int mf = 0; mf < 2; mf++) {
            const int r0 = warp_m * 32 + mf * 16 + g;
            uint2 v0 = *(const uint2*)&As[r0 * 64 + idxp];
            uint2 v1 = *(const uint2*)&As[(r0 + 8) * 64 + idxp];
            Afrag[mf][0] = v0.x; Afrag[mf][2] = v0.y;
            Afrag[mf][1] = v1.x; Afrag[mf][3] = v1.y;
        }
        uint32_t Bfrag[8][2];
#pragma unroll
        for (int nf = 0; nf < 8; nf++) {
            const int n0 = warp_n * 64 + nf * 8 + g;
            uint2 v = *(const uint2*)&Bs[n0 * 64 + idxp];
            Bfrag[nf][0] = v.x; Bfrag[nf][1] = v.y;
        }
#pragma unroll
        for (int mf = 0; mf < 2; mf++)
#pragma unroll
            for (int nf = 0; nf < 8; nf++)
                mma_tf32(acc[mf][nf], Afrag[mf], Bfrag[nf]);
    }

#pragma unroll
    for (int mf = 0; mf < 2; mf++) {
        const int r0 = row0 + warp_m * 32 + mf * 16 + g;
#pragma unroll
        for (int nf = 0; nf < 8; nf++) {
            const int c = col0 + warp_n * 64 + nf * 8 + 2 * tig;
            if (r0 < M)
                *(__half2*)(C + (size_t)r0 * HW + c) =
                    __floats2half2_rn(acc[mf][nf][0], acc[mf][nf][1]);
            if (r0 + 8 < M)
                *(__half2*)(C + (size_t)(r0 + 8) * HW + c) =
                    __floats2half2_rn(acc[mf][nf][2], acc[mf][nf][3]);
        }
    }
}

// ---------------- tiled fp32 GEMM (embeddings) -------------------------------
__global__ void gemm_tiled(const float* __restrict__ A, int lda,
                           const float* __restrict__ W, int ldw,
                           const float* __restrict__ bias,
                           float* __restrict__ C, int ldc,
                           int M, int K, int act)
{
    __shared__ float As[16][64];
    __shared__ float Ws[16][64];
    const int row0 = blockIdx.x * 64;
    const int col0 = blockIdx.y * 64;
    const int tid = threadIdx.x;
    const int tx = tid & 15, ty = tid >> 4;

    float acc[4][4];
#pragma unroll
    for (int i = 0; i < 4; i++)
#pragma unroll
        for (int j = 0; j < 4; j++) acc[i][j] = 0.f;

    for (int k0 = 0; k0 < K; k0 += 16) {
#pragma unroll
        for (int i = 0; i < 4; i++) {
            int e = tid + 256 * i;
            int r = e >> 4, kk = e & 15;
            int gr = row0 + r, gk = k0 + kk;
            As[kk][r] = (gr < M && gk < K) ? A[(size_t)gr * lda + gk] : 0.f;
        }
#pragma unroll
        for (int i = 0; i < 4; i++) {
            int e = tid + 256 * i;
            int kk = e >> 6, c = e & 63;
            int gk = k0 + kk;
            Ws[kk][c] = (gk < K) ? W[(size_t)gk * ldw + col0 + c] : 0.f;
        }
        __syncthreads();
#pragma unroll
        for (int kk = 0; kk < 16; kk++) {
            float4 a = *(const float4*)&As[kk][ty * 4];
            float4 b = *(const float4*)&Ws[kk][tx * 4];
            float av[4] = {a.x, a.y, a.z, a.w};
            float bv[4] = {b.x, b.y, b.z, b.w};
#pragma unroll
            for (int i = 0; i < 4; i++)
#pragma unroll
                for (int j = 0; j < 4; j++) acc[i][j] += av[i] * bv[j];
        }
        __syncthreads();
    }
#pragma unroll
    for (int i = 0; i < 4; i++) {
        int r = row0 + ty * 4 + i;
        if (r >= M) continue;
#pragma unroll
        for (int j = 0; j < 4; j++) {
            int c = col0 + tx * 4 + j;
            float v = acc[i][j];
            if (bias) v += bias[c];
            if (act) v = lrelu(v);
            C[(size_t)r * ldc + c] = v;
        }
    }
}

// ---------------- per-edge GAT kernel (warp per edge, fp16 P & Q) ------------
__global__ void edge_kernel(const int* __restrict__ rowi, const int* __restrict__ coli,
                            const float* __restrict__ att,
                            const float* __restrict__ gamma,
                            const float* __restrict__ beta,
                            int E)
{
    int e = (blockIdx.x * blockDim.x + threadIdx.x) >> 5;
    if (e >= E) return;
    const int l = threadIdx.x & 31;
    const int r = rowi[e], c = coli[e];
    const __half2* pr = (const __half2*)(g_Ph + (size_t)r * HW);
    const __half2* pc = (const __half2*)(g_Ph + (size_t)c * HW);
    const __half2* q  = (const __half2*)(g_Qh + (size_t)e * HW);
    const float2*  at = (const float2*)att;

    float2 hj[NHEAD];
    float alpha[NHEAD];
#pragma unroll
    for (int nh = 0; nh < NHEAD; nh++) {
        float2 qv  = __half22float2(q[nh * 32 + l]);
        float2 prv = __half22float2(pr[nh * 32 + l]);
        float2 pcv = __half22float2(pc[nh * 32 + l]);
        float hi0 = lrelu(prv.x + qv.x), hi1 = lrelu(prv.y + qv.y);
        float hj0 = lrelu(pcv.x + qv.x), hj1 = lrelu(pcv.y + qv.y);
        hj[nh].x = hj0; hj[nh].y = hj1;
        float2 a1 = at[nh * 64 + l];
        float2 a2 = at[nh * 64 + 32 + l];
        float part = hi0 * a1.x + hi1 * a1.y + hj0 * a2.x + hj1 * a2.y;
#pragma unroll
        for (int o = 16; o; o >>= 1) part += __shfl_xor_sync(0xffffffffu, part, o);
        alpha[nh] = part;
    }
    const float inv_std = 0.9999950000374997f;  // 1/sqrt(1+1e-5)
    float mx = -1e30f;
#pragma unroll
    for (int nh = 0; nh < NHEAD; nh++) {
        float a = lrelu(alpha[nh]);
        a = a * inv_std * gamma[nh] + beta[nh];
        alpha[nh] = a;
        mx = fmaxf(mx, a);
    }
    float s = 0.f;
#pragma unroll
    for (int nh = 0; nh < NHEAD; nh++) { float ev = expf(alpha[nh] - mx); alpha[nh] = ev; s += ev; }
    float inv = 0.1f / s;
    float m0 = 0.f, m1 = 0.f;
#pragma unroll
    for (int nh = 0; nh < NHEAD; nh++) { m0 += hj[nh].x * alpha[nh]; m1 += hj[nh].y * alpha[nh]; }
    m0 *= inv; m1 *= inv;
    atomicAdd(&g_hagg[r * HD + 2 * l],     m0);
    atomicAdd(&g_hagg[r * HD + 2 * l + 1], m1);
}

// ---------------- node update (+ zero hagg for next layer; + tf32 perm) ------
__global__ void node_update(const float* __restrict__ b, int N, int first, int last)
{
    int idx = blockIdx.x * blockDim.x + threadIdx.x;
    if (idx >= N * HD) return;
    int k = idx & (HD - 1);
    int row = idx >> 6;
    float v = g_hagg[idx] + b[k];
    g_hagg[idx] = 0.f;                       // ready for next layer / next replay
    float h = first ? v : (g_h[idx] + v);
    if (last) h += g_h0[idx];
    g_h[idx] = h;
    g_ht[row * HD + perm_col(k)] = tf32_rnd(h);
}

// ---------------- readout ----------------------------------------------------
__global__ void gb_kernel(const float* __restrict__ gf, const float* __restrict__ W1,
                          const float* __restrict__ b1, int G)
{
    int g = blockIdx.x;
    int k = threadIdx.x;
    float acc = b1[k];
    const float* gr = gf + (size_t)g * GD;
    for (int j = 0; j < GD; j++) acc += gr[j] * W1[(64 + j) * HD + k];
    g_GB[g * HD + k] = acc;
}

__global__ void score_kernel(const int* __restrict__ batch,
                             const float* __restrict__ W1,
                             const float* __restrict__ W2, const float* __restrict__ b2,
                             int N)
{
    int n = (blockIdx.x * blockDim.x + threadIdx.x) >> 5;
    if (n >= N) return;
    int l = threadIdx.x & 31;
    int b = batch[n];
    int k0 = 2 * l;
    float s0 = g_GB[b * HD + k0], s1 = g_GB[b * HD + k0 + 1];
    const float* hr = g_h + (size_t)n * HD;
#pragma unroll 8
    for (int j = 0; j < HD; j++) {
        float hv = hr[j];
        s0 += hv * W1[j * HD + k0];
        s1 += hv * W1[j * HD + k0 + 1];
    }
    s0 = lrelu(s0); s1 = lrelu(s1);
    float part = s0 * W2[k0] + s1 * W2[k0 + 1];
#pragma unroll
    for (int o = 16; o; o >>= 1) part += __shfl_xor_sync(0xffffffffu, part, o);
    if (l == 0) {
        float sc = part + b2[0];
        g_score[n] = sc;
        atomicMax(&g_smax[b], f2o(sc));
    }
}

__global__ void exp_kernel(const int* __restrict__ batch, int N)
{
    int n = blockIdx.x * blockDim.x + threadIdx.x;
    if (n >= N) return;
    int b = batch[n];
    float ev = expf(g_score[n] - o2f(g_smax[b]));
    g_ex[n] = ev;
    atomicAdd(&g_denom[b], ev);
}

__global__ void pool_kernel(const int* __restrict__ batch, int N)
{
    int n = (blockIdx.x * blockDim.x + threadIdx.x) >> 5;
    if (n >= N) return;
    int l = threadIdx.x & 31;
    int b = batch[n];
    float w = g_ex[n] / g_denom[b];
    int k0 = 2 * l;
    atomicAdd(&g_pooled[b * HD + k0],     g_h[(size_t)n * HD + k0] * w);
    atomicAdd(&g_pooled[b * HD + k0 + 1], g_h[(size_t)n * HD + k0 + 1] * w);
}

__global__ void out_kernel(const float* __restrict__ W1, const float* __restrict__ b1,
                           const float* __restrict__ W2, const float* __restrict__ b2,
                           float* __restrict__ out)
{
    int g = blockIdx.x;
    int k = threadIdx.x;
    __shared__ float ps[HD];
    __shared__ float red[HD];
    ps[k] = g_pooled[g * HD + k];
    __syncthreads();
    float acc = b1[k];
#pragma unroll 8
    for (int j = 0; j < HD; j++) acc += ps[j] * W1[j * HD + k];
    acc = fmaxf(acc, 0.f);
    red[k] = acc * W2[k];
    __syncthreads();
    for (int o = 32; o; o >>= 1) {
        if (k < o) red[k] += red[k + o];
        __syncthreads();
    }
    if (k == 0) out[g] = red[0] + b2[0];
}

// ---------------- host launcher ---------------------------------------------
extern "C" void kernel_launch(void* const* d_in, const int* in_sizes, int n_in,
                              void* d_out, int out_size)
{
    const float* x      = (const float*)d_in[0];
    const int*   eidx   = (const int*)  d_in[1];
    const float* eattr  = (const float*)d_in[2];
    const int*   batch  = (const int*)  d_in[3];
    const float* gfeat  = (const float*)d_in[4];
    const float* node_W = (const float*)d_in[5];
    const float* node_b = (const float*)d_in[6];
    const float* edge_W = (const float*)d_in[7];
    const float* edge_b = (const float*)d_in[8];
    const float* conv_W = (const float*)d_in[9];
    const float* conv_att = (const float*)d_in[10];
    const float* conv_b = (const float*)d_in[11];
    const float* conv_g = (const float*)d_in[12];
    const float* conv_be = (const float*)d_in[13];
    const float* ga_W1  = (const float*)d_in[14];
    const float* ga_b1  = (const float*)d_in[15];
    const float* ga_W2  = (const float*)d_in[16];
    const float* ga_b2  = (const float*)d_in[17];
    const float* out_W1 = (const float*)d_in[18];
    const float* out_b1 = (const float*)d_in[19];
    const float* out_W2 = (const float*)d_in[20];
    const float* out_b2 = (const float*)d_in[21];

    const int N = in_sizes[3];
    const int E = in_sizes[2] / EF;
    const int G = in_sizes[4] / GD;

    const int* row = eidx;
    const int* col = eidx + E;

    float *p_h, *p_h0, *p_ea, *p_hagg, *p_denom, *p_pooled;
    float *p_Wt, *p_eat, *p_ht;
    __half *p_Ph, *p_Qh;
    unsigned* p_smax;
    cudaGetSymbolAddress((void**)&p_h,     g_h);
    cudaGetSymbolAddress((void**)&p_h0,    g_h0);
    cudaGetSymbolAddress((void**)&p_ea,    g_ea);
    cudaGetSymbolAddress((void**)&p_Ph,    g_Ph);
    cudaGetSymbolAddress((void**)&p_Qh,    g_Qh);
    cudaGetSymbolAddress((void**)&p_hagg,  g_hagg);
    cudaGetSymbolAddress((void**)&p_smax,  g_smax);
    cudaGetSymbolAddress((void**)&p_denom, g_denom);
    cudaGetSymbolAddress((void**)&p_pooled,g_pooled);
    cudaGetSymbolAddress((void**)&p_Wt,    g_Wt);
    cudaGetSymbolAddress((void**)&p_eat,   g_eat);
    cudaGetSymbolAddress((void**)&p_ht,    g_ht);

    cudaFuncSetAttribute(gemm_mma, cudaFuncAttributeMaxDynamicSharedMemorySize,
                         GEMM_SMEM);

    // embeddings (fp32)
    {
        dim3 grid((N + 63) / 64, HD / 64);
        gemm_tiled<<<grid, 256>>>(x, NF, node_W, HD, node_b, p_h0, HD, N, NF, 1);
    }
    {
        dim3 grid((E + 63) / 64, HD / 64);
        gemm_tiled<<<grid, 256>>>(eattr, EF, edge_W, HD, edge_b, p_ea, HD, E, EF, 1);
    }

    // prep: conv weights (transpose+round+perm); edge & initial node embeddings
    prep_W<<<(NL * 2 * HW * HD + 255) / 256, 256>>>(conv_W);
    round_perm<<<(E * HD + 255) / 256, 256>>>(p_ea, p_eat, E * HD);
    round_perm<<<(N * HD + 255) / 256, 256>>>(p_h0, p_ht, N * HD);

    const int nb1 = (N + 127) / 128;
    const int nb2 = (E + 127) / 128;

    for (int i = 0; i < NL; i++) {
        const float* attL = conv_att + (size_t)i * NHEAD * 2 * HD;
        const float* bL   = conv_b + i * HD;
        const float* gmL  = conv_g + i * NHEAD;
        const float* btL  = conv_be + i * NHEAD;

        const float* WP = p_Wt + (size_t)(i * 2 + 0) * HW * HD;
        const float* WQ = p_Wt + (size_t)(i * 2 + 1) * HW * HD;

        dim3 gridPQ(nb1 + nb2, HW / 128);
        gemm_mma<<<gridPQ, 256, GEMM_SMEM>>>(p_ht, p_eat, WP, WQ, p_Ph, p_Qh,
                                             N, E, nb1);

        int blocks = (E * 32 + 255) / 256;
        edge_kernel<<<blocks, 256>>>(row, col, attL, gmL, btL, E);

        node_update<<<(N * HD + 255) / 256, 256>>>(bL, N, i == 0, i == NL - 1);
    }

    // readout
    cudaMemsetAsync(p_smax, 0, G * sizeof(unsigned));
    cudaMemsetAsync(p_denom, 0, G * sizeof(float));
    cudaMemsetAsync(p_pooled, 0, (size_t)G * HD * sizeof(float));

    gb_kernel<<<G, HD>>>(gfeat, ga_W1, ga_b1, G);
    score_kernel<<<(N * 32 + 255) / 256, 256>>>(batch, ga_W1, ga_W2, ga_b2, N);
    exp_kernel<<<(N + 255) / 256, 256>>>(batch, N);
    pool_kernel<<<(N * 32 + 255) / 256, 256>>>(batch, N);
    out_kernel<<<G, HD>>>(out_W1, out_b1, out_W2, out_b2, (float*)d_out);
}